// round 13
// baseline (speedup 1.0000x reference)
#include <cuda_runtime.h>
#include <math.h>

#define Bsz 512
#define Tt  1024
#define Dd  64
#define Hh  64
#define Rr  4
#define MHh 32
#define PCH 16

typedef unsigned long long ull;

// xg scratch, plain row order: xg[t][b][row], bias baked in. 512MB.
__device__ float xg_buf[(size_t)Tt * Bsz * 256];

__device__ __forceinline__ void fma2(ull &d, ull a, ull b){
    asm("fma.rn.f32x2 %0, %1, %2, %0;" : "+l"(d) : "l"(a), "l"(b));
}
__device__ __forceinline__ ull pack2(float lo, float hi){
    ull r; asm("mov.b64 %0, {%1, %2};" : "=l"(r) : "f"(lo), "f"(hi)); return r;
}
__device__ __forceinline__ float2 unpack2(ull v){
    float2 r; asm("mov.b64 {%0, %1}, %2;" : "=f"(r.x), "=f"(r.y) : "l"(v)); return r;
}

__device__ __forceinline__ float fsigmoid(float v){
    float e = __expf(-v);
    return __fdividef(1.0f, 1.0f + e);
}
// Saturation-safe: exp argument always <= 0.
__device__ __forceinline__ float ftanh(float v){
    float t = __expf(-2.0f * fabsf(v));
    float r = __fdividef(1.0f - t, 1.0f + t);
    return copysignf(r, v);
}

// ---------------------------------------------------------------------------
// Input projection (round-12, double-buffered): thread j owns rows 2j, 2j+1.
// ---------------------------------------------------------------------------
__global__ __launch_bounds__(128)
void proj_kernel(const float* __restrict__ x,
                 const float* __restrict__ W_ih,
                 const float* __restrict__ b_ih,
                 const float* __restrict__ b_hh)
{
    const int j  = threadIdx.x;
    const int r0 = 2*j, r1 = 2*j + 1;
    const int b  = blockIdx.x >> 2;
    const int t0 = (blockIdx.x & 3) * 256;

    __shared__ __align__(16) float xsh[2][PCH][Dd];

    ull w0[Dd/2], w1[Dd/2];
#pragma unroll
    for (int k = 0; k < Dd/2; k += 2){
        ulonglong2 a = *(const ulonglong2*)&W_ih[r0 * Dd + 2*k];
        w0[k] = a.x; w0[k+1] = a.y;
        ulonglong2 c = *(const ulonglong2*)&W_ih[r1 * Dd + 2*k];
        w1[k] = c.x; w1[k+1] = c.y;
    }
    const float bj0 = b_ih[r0] + b_hh[r0];
    const float bj1 = b_ih[r1] + b_hh[r1];

    const float4* xbase = (const float4*)(x + ((size_t)b * Tt + t0) * Dd);
    const int CHUNK4 = PCH * Dd / 4;

    {
        float4 pa = xbase[j], pb = xbase[j + 128];
        float4* dst = (float4*)&xsh[0][0][0];
        dst[j] = pa; dst[j + 128] = pb;
    }
    __syncthreads();

    for (int c = 0; c < 256 / PCH; c++){
        const int pb_ = c & 1;
        float4 pa, pbv;
        if (c + 1 < 256 / PCH){
            const float4* src = xbase + (size_t)(c + 1) * CHUNK4;
            pa  = src[j];
            pbv = src[j + 128];
        }

#pragma unroll 4
        for (int p = 0; p < PCH; p++){
            const ulonglong2* v = (const ulonglong2*)&xsh[pb_][p][0];
            ull a00 = 0ULL, a01 = 0ULL, a10 = 0ULL, a11 = 0ULL;
#pragma unroll
            for (int q = 0; q < 16; q++){
                ulonglong2 xx = v[q];
                fma2(a00, w0[2*q    ], xx.x);
                fma2(a01, w0[2*q + 1], xx.y);
                fma2(a10, w1[2*q    ], xx.x);
                fma2(a11, w1[2*q + 1], xx.y);
            }
            float2 p0 = unpack2(a00), p1 = unpack2(a01);
            float2 p2 = unpack2(a10), p3 = unpack2(a11);
            size_t base = ((size_t)(t0 + c * PCH + p) * Bsz + b) * 256;
            float2 o;
            o.x = bj0 + ((p0.x + p1.x) + (p0.y + p1.y));
            o.y = bj1 + ((p2.x + p3.x) + (p2.y + p3.y));
            *(float2*)&xg_buf[base + 2*j] = o;
        }

        if (c + 1 < 256 / PCH){
            float4* dst = (float4*)&xsh[pb_ ^ 1][0][0];
            dst[j] = pa; dst[j + 128] = pbv;
        }
        __syncthreads();
    }
}

// ---------------------------------------------------------------------------
// FUSED recurrence + heads. Rec core = round-9 v3 (verified, ~650us).
// Every 64 steps: heads burst — thread owns 1 fresh (b,t) point, reads its
// y row from gmem (visible via __syncthreads' gmem ordering), runs the
// verified heads math against all-heads weights staged once in 50.7KB smem.
// ---------------------------------------------------------------------------
__global__ __launch_bounds__(128, 2)
void lstm_fused_kernel(const float* __restrict__ h_init,
                       const float* __restrict__ c_init,
                       const float* __restrict__ W_hh,
                       const float* __restrict__ W1, const float* __restrict__ b1,
                       const float* __restrict__ W2, const float* __restrict__ b2,
                       const float* __restrict__ W3, const float* __restrict__ b3,
                       float* y, float* outs)
{
    extern __shared__ float sm[];
    float* W1s = sm;                 // 8192
    float* W2s = W1s + 8192;         // 4096
    float* W3s = W2s + 4096;         // 128
    float* b1s = W3s + 128;          // 128
    float* b2s = b1s + 128;          // 128
    float* b3s = b2s + 128;          // 8 (pad)

    __shared__ __align__(16) float hs[2][2][Hh];

    const int tid  = threadIdx.x;
    const int w    = tid >> 5;
    const int l    = tid & 31;
    const int half = l >> 4;               // 0: (i,g)+batch0, 1: (f,o)+batch1
    const int u    = (w << 4) + (l & 15);  // unit 0..63
    const int rA   = half ? (64 + u) : u;          // f : i
    const int rB   = half ? (192 + u) : (128 + u); // o : g
    const int b0   = blockIdx.x * 2;
    const size_t BT = (size_t)Bsz * Tt;

    // stage ALL heads weights once
    for (int i = tid; i < Rr*MHh*Hh;  i += 128) W1s[i] = W1[i];
    for (int i = tid; i < Rr*MHh*MHh; i += 128) W2s[i] = W2[i];
    if (tid < Rr*MHh){ W3s[tid] = W3[tid]; b1s[tid] = b1[tid]; b2s[tid] = b2[tid]; }
    if (tid < Rr) b3s[tid] = b3[tid];

    ull wA[Hh/2], wB[Hh/2];
#pragma unroll
    for (int k = 0; k < Hh/2; k += 2){
        ulonglong2 a = *(const ulonglong2*)&W_hh[rA * Hh + 2*k];
        wA[k] = a.x; wA[k+1] = a.y;
        ulonglong2 c = *(const ulonglong2*)&W_hh[rB * Hh + 2*k];
        wB[k] = c.x; wB[k+1] = c.y;
    }

    float creg = c_init[u];                // state (batch = half, unit = u)
    hs[0][half][u] = h_init[u];

    float xA0 = xg_buf[(size_t)(b0    ) * 256 + rA];
    float xB0 = xg_buf[(size_t)(b0    ) * 256 + rB];
    float xA1 = xg_buf[(size_t)(b0 + 1) * 256 + rA];
    float xB1 = xg_buf[(size_t)(b0 + 1) * 256 + rB];
    __syncthreads();

    // burst-point identity: thread -> (batch bl, local t tl)
    const int bl = tid >> 6;
    const int tl = tid & 63;

#pragma unroll 1
    for (int t = 0; t < Tt; t++){
        const int pr = t & 1;
        float cA0 = xA0, cB0 = xB0, cA1 = xA1, cB1 = xB1;
        if (t + 1 < Tt){
            size_t base = ((size_t)(t + 1) * Bsz + b0) * 256;
            xA0 = xg_buf[base + rA];
            xB0 = xg_buf[base + rB];
            xA1 = xg_buf[base + 256 + rA];
            xB1 = xg_buf[base + 256 + rB];
        }

        ull aA0a=0,aA0b=0,aB0a=0,aB0b=0,aA1a=0,aA1b=0,aB1a=0,aB1b=0;
#pragma unroll
        for (int k = 0; k < Hh; k += 4){
            ulonglong2 v0 = *(const ulonglong2*)&hs[pr][0][k];
            ulonglong2 v1 = *(const ulonglong2*)&hs[pr][1][k];
            fma2(aA0a, wA[k/2    ], v0.x);
            fma2(aA0b, wA[k/2 + 1], v0.y);
            fma2(aB0a, wB[k/2    ], v0.x);
            fma2(aB0b, wB[k/2 + 1], v0.y);
            fma2(aA1a, wA[k/2    ], v1.x);
            fma2(aA1b, wA[k/2 + 1], v1.y);
            fma2(aB1a, wB[k/2    ], v1.x);
            fma2(aB1b, wB[k/2 + 1], v1.y);
        }
        float2 q0, q1;
        q0 = unpack2(aA0a); q1 = unpack2(aA0b);
        float gA0 = cA0 + ((q0.x + q1.x) + (q0.y + q1.y));
        q0 = unpack2(aB0a); q1 = unpack2(aB0b);
        float gB0 = cB0 + ((q0.x + q1.x) + (q0.y + q1.y));
        q0 = unpack2(aA1a); q1 = unpack2(aA1b);
        float gA1 = cA1 + ((q0.x + q1.x) + (q0.y + q1.y));
        q0 = unpack2(aB1a); q1 = unpack2(aB1b);
        float gB1 = cB1 + ((q0.x + q1.x) + (q0.y + q1.y));

        float aA0 = fsigmoid(gA0);
        float aA1 = fsigmoid(gA1);
        float aB0 = half ? fsigmoid(gB0) : ftanh(gB0);
        float aB1 = half ? fsigmoid(gB1) : ftanh(gB1);

        float pA0 = __shfl_xor_sync(0xffffffffu, aA0, 16);
        float pB0 = __shfl_xor_sync(0xffffffffu, aB0, 16);
        float pA1 = __shfl_xor_sync(0xffffffffu, aA1, 16);
        float pB1 = __shfl_xor_sync(0xffffffffu, aB1, 16);

        float ig = half ? pA1 : aA0;
        float fg = half ? aA1 : pA0;
        float gg = half ? pB1 : aB0;
        float og = half ? aB1 : pB0;

        float cn = fmaf(fg, creg, ig * gg);
        creg = cn;
        float hn = og * ftanh(cn);
        hs[pr ^ 1][half][u] = hn;
        y[((size_t)(b0 + half)) * Tt * Hh + (size_t)t * Hh + u] = hn;

        __syncthreads();   // orders y STGs (gmem) before the burst's LDGs

        // ---- heads burst every 64 steps: 1 point per thread ----
        if ((t & 63) == 63){
            const size_t bt = ((size_t)(b0 + bl)) * Tt + (size_t)(t - 63 + tl);
            ull yv[Hh/2];
            const ulonglong2* yp = (const ulonglong2*)(y + bt * Hh);
#pragma unroll
            for (int q = 0; q < 16; q++){
                ulonglong2 vv = yp[q];
                yv[2*q] = vv.x; yv[2*q + 1] = vv.y;
            }

#pragma unroll 1
            for (int r = 0; r < Rr; r++){
                ull h1p[MHh/2];
#pragma unroll
                for (int m = 0; m < MHh; m += 2){
                    float hm[2];
#pragma unroll
                    for (int mm = 0; mm < 2; mm++){
                        const ulonglong2* wp = (const ulonglong2*)(W1s + (r*MHh + m + mm) * Hh);
                        ull a0 = 0ULL, a1 = 0ULL, a2 = 0ULL, a3 = 0ULL;
#pragma unroll
                        for (int q = 0; q < 8; q++){
                            ulonglong2 wa = wp[2*q    ];
                            ulonglong2 wb = wp[2*q + 1];
                            fma2(a0, wa.x, yv[4*q    ]);
                            fma2(a1, wa.y, yv[4*q + 1]);
                            fma2(a2, wb.x, yv[4*q + 2]);
                            fma2(a3, wb.y, yv[4*q + 3]);
                        }
                        float2 p0 = unpack2(a0), p1 = unpack2(a1);
                        float2 p2 = unpack2(a2), p3 = unpack2(a3);
                        float s = ((p0.x + p1.x) + (p0.y + p1.y)) + ((p2.x + p3.x) + (p2.y + p3.y));
                        hm[mm] = fmaxf(b1s[r*MHh + m + mm] + s, 0.0f);
                    }
                    h1p[m/2] = pack2(hm[0], hm[1]);
                }

                ull h2p[MHh/2];
#pragma unroll
                for (int n = 0; n < MHh; n += 2){
                    float hv[2];
#pragma unroll
                    for (int nn = 0; nn < 2; nn++){
                        const ulonglong2* wp = (const ulonglong2*)(W2s + (r*MHh + n + nn) * MHh);
                        ull a0 = 0ULL, a1 = 0ULL, a2 = 0ULL, a3 = 0ULL;
#pragma unroll
                        for (int q = 0; q < 4; q++){
                            ulonglong2 wa = wp[2*q    ];
                            ulonglong2 wb = wp[2*q + 1];
                            fma2(a0, wa.x, h1p[4*q    ]);
                            fma2(a1, wa.y, h1p[4*q + 1]);
                            fma2(a2, wb.x, h1p[4*q + 2]);
                            fma2(a3, wb.y, h1p[4*q + 3]);
                        }
                        float2 p0 = unpack2(a0), p1 = unpack2(a1);
                        float2 p2 = unpack2(a2), p3 = unpack2(a3);
                        float s = ((p0.x + p1.x) + (p0.y + p1.y)) + ((p2.x + p3.x) + (p2.y + p3.y));
                        hv[nn] = fmaxf(b2s[r*MHh + n + nn] + s, 0.0f);
                    }
                    h2p[n/2] = pack2(hv[0], hv[1]);
                }

                {
                    const ulonglong2* wp = (const ulonglong2*)(W3s + r * MHh);
                    ull a0 = 0ULL, a1 = 0ULL, a2 = 0ULL, a3 = 0ULL;
#pragma unroll
                    for (int q = 0; q < 4; q++){
                        ulonglong2 wa = wp[2*q    ];
                        ulonglong2 wb = wp[2*q + 1];
                        fma2(a0, wa.x, h2p[4*q    ]);
                        fma2(a1, wa.y, h2p[4*q + 1]);
                        fma2(a2, wb.x, h2p[4*q + 2]);
                        fma2(a3, wb.y, h2p[4*q + 3]);
                    }
                    float2 p0 = unpack2(a0), p1 = unpack2(a1);
                    float2 p2 = unpack2(a2), p3 = unpack2(a3);
                    float s = ((p0.x + p1.x) + (p0.y + p1.y)) + ((p2.x + p3.x) + (p2.y + p3.y));
                    outs[(size_t)r * BT + bt] = b3s[r] + s;
                }
            }
        }
    }
}

extern "C" void kernel_launch(void* const* d_in, const int* in_sizes, int n_in,
                              void* d_out, int out_size)
{
    const float* x      = (const float*)d_in[0];
    const float* h_init = (const float*)d_in[1];
    const float* c_init = (const float*)d_in[2];
    const float* W_ih   = (const float*)d_in[3];
    const float* W_hh   = (const float*)d_in[4];
    const float* b_ih   = (const float*)d_in[5];
    const float* b_hh   = (const float*)d_in[6];
    const float* W1     = (const float*)d_in[7];
    const float* b1     = (const float*)d_in[8];
    const float* W2     = (const float*)d_in[9];
    const float* b2     = (const float*)d_in[10];
    const float* W3     = (const float*)d_in[11];
    const float* b3     = (const float*)d_in[12];

    float* y    = (float*)d_out;                     // (B, T, H)
    float* outs = y + (size_t)Bsz * Tt * Hh;         // (R, B, T)

    proj_kernel<<<Bsz * 4, 128>>>(x, W_ih, b_ih, b_hh);

    const size_t shmem = 12688 * sizeof(float);      // 50752 B
    cudaFuncSetAttribute(lstm_fused_kernel,
                         cudaFuncAttributeMaxDynamicSharedMemorySize, (int)shmem);
    lstm_fused_kernel<<<Bsz / 2, 128, shmem>>>(h_init, c_init, W_hh,
                                               W1, b1, W2, b2, W3, b3, y, outs);
}

// round 14
// speedup vs baseline: 1.3524x; 1.3524x over previous
#include <cuda_runtime.h>
#include <math.h>

#define Bsz 512
#define Tt  1024
#define Dd  64
#define Hh  64
#define Rr  4
#define MHh 32
#define PCH 16

typedef unsigned long long ull;

// xg scratch, plain row order: xg[t][b][row], bias baked in. 512MB.
__device__ float xg_buf[(size_t)Tt * Bsz * 256];

__device__ __forceinline__ void fma2(ull &d, ull a, ull b){
    asm("fma.rn.f32x2 %0, %1, %2, %0;" : "+l"(d) : "l"(a), "l"(b));
}
__device__ __forceinline__ ull pack2(float lo, float hi){
    ull r; asm("mov.b64 %0, {%1, %2};" : "=l"(r) : "f"(lo), "f"(hi)); return r;
}
__device__ __forceinline__ float2 unpack2(ull v){
    float2 r; asm("mov.b64 {%0, %1}, %2;" : "=f"(r.x), "=f"(r.y) : "l"(v)); return r;
}

__device__ __forceinline__ float fsigmoid(float v){
    float e = __expf(-v);
    return __fdividef(1.0f, 1.0f + e);
}
// Saturation-safe: exp argument always <= 0.
__device__ __forceinline__ float ftanh(float v){
    float t = __expf(-2.0f * fabsf(v));
    float r = __fdividef(1.0f - t, 1.0f + t);
    return copysignf(r, v);
}

// ---------------------------------------------------------------------------
// Input projection (round-12, double-buffered): thread j owns rows 2j, 2j+1.
// ---------------------------------------------------------------------------
__global__ __launch_bounds__(128)
void proj_kernel(const float* __restrict__ x,
                 const float* __restrict__ W_ih,
                 const float* __restrict__ b_ih,
                 const float* __restrict__ b_hh)
{
    const int j  = threadIdx.x;
    const int r0 = 2*j, r1 = 2*j + 1;
    const int b  = blockIdx.x >> 2;
    const int t0 = (blockIdx.x & 3) * 256;

    __shared__ __align__(16) float xsh[2][PCH][Dd];

    ull w0[Dd/2], w1[Dd/2];
#pragma unroll
    for (int k = 0; k < Dd/2; k += 2){
        ulonglong2 a = *(const ulonglong2*)&W_ih[r0 * Dd + 2*k];
        w0[k] = a.x; w0[k+1] = a.y;
        ulonglong2 c = *(const ulonglong2*)&W_ih[r1 * Dd + 2*k];
        w1[k] = c.x; w1[k+1] = c.y;
    }
    const float bj0 = b_ih[r0] + b_hh[r0];
    const float bj1 = b_ih[r1] + b_hh[r1];

    const float4* xbase = (const float4*)(x + ((size_t)b * Tt + t0) * Dd);
    const int CHUNK4 = PCH * Dd / 4;

    {
        float4 pa = xbase[j], pb = xbase[j + 128];
        float4* dst = (float4*)&xsh[0][0][0];
        dst[j] = pa; dst[j + 128] = pb;
    }
    __syncthreads();

    for (int c = 0; c < 256 / PCH; c++){
        const int pb_ = c & 1;
        float4 pa, pbv;
        if (c + 1 < 256 / PCH){
            const float4* src = xbase + (size_t)(c + 1) * CHUNK4;
            pa  = src[j];
            pbv = src[j + 128];
        }

#pragma unroll 4
        for (int p = 0; p < PCH; p++){
            const ulonglong2* v = (const ulonglong2*)&xsh[pb_][p][0];
            ull a00 = 0ULL, a01 = 0ULL, a10 = 0ULL, a11 = 0ULL;
#pragma unroll
            for (int q = 0; q < 16; q++){
                ulonglong2 xx = v[q];
                fma2(a00, w0[2*q    ], xx.x);
                fma2(a01, w0[2*q + 1], xx.y);
                fma2(a10, w1[2*q    ], xx.x);
                fma2(a11, w1[2*q + 1], xx.y);
            }
            float2 p0 = unpack2(a00), p1 = unpack2(a01);
            float2 p2 = unpack2(a10), p3 = unpack2(a11);
            size_t base = ((size_t)(t0 + c * PCH + p) * Bsz + b) * 256;
            float2 o;
            o.x = bj0 + ((p0.x + p1.x) + (p0.y + p1.y));
            o.y = bj1 + ((p2.x + p3.x) + (p2.y + p3.y));
            *(float2*)&xg_buf[base + 2*j] = o;
        }

        if (c + 1 < 256 / PCH){
            float4* dst = (float4*)&xsh[pb_ ^ 1][0][0];
            dst[j] = pa; dst[j + 128] = pbv;
        }
        __syncthreads();
    }
}

#define BAR_REC()  asm volatile("bar.sync 1, 128;" ::: "memory")
#define BAR_ALL()  asm volatile("bar.sync 2, 256;" ::: "memory")

// ---------------------------------------------------------------------------
// Warp-specialized fused kernel: 128 blocks x 256 threads (occ 1, all
// resident). Warps 4-7 (HIGH wid = arbiter priority): v3 recurrence for 4
// batches, named barrier 1 only. Warps 0-3: heads bursts, handed a 128-point
// tile (4 batches x 32 t) by a block-wide bar.sync 2 every 32 steps.
// ---------------------------------------------------------------------------
__global__ __launch_bounds__(256, 1)
void fused_kernel(const float* __restrict__ h_init,
                  const float* __restrict__ c_init,
                  const float* __restrict__ W_hh,
                  const float* __restrict__ W1, const float* __restrict__ b1,
                  const float* __restrict__ W2, const float* __restrict__ b2,
                  const float* __restrict__ W3, const float* __restrict__ b3,
                  float* y, float* outs)
{
    extern __shared__ float sm[];
    float* W1s = sm;                 // 8192
    float* W2s = W1s + 8192;         // 4096
    float* W3s = W2s + 4096;         // 128
    float* b1s = W3s + 128;          // 128
    float* b2s = b1s + 128;          // 128
    float* b3s = b2s + 128;          // 8 (pad)

    __shared__ __align__(16) float hs[2][4][Hh];

    const int tid = threadIdx.x;
    const int b0  = blockIdx.x * 4;
    const size_t BT = (size_t)Bsz * Tt;

    if (tid < 128){
        // heads warps stage ALL heads weights
        for (int i = tid; i < Rr*MHh*Hh;  i += 128) W1s[i] = W1[i];
        for (int i = tid; i < Rr*MHh*MHh; i += 128) W2s[i] = W2[i];
        W3s[tid] = W3[tid]; b1s[tid] = b1[tid]; b2s[tid] = b2[tid];
        if (tid < Rr) b3s[tid] = b3[tid];
    }

    if (tid >= 128){
        // =================== RECURRENCE (warps 4-7) ===================
        const int rt   = tid - 128;
        const int w    = rt >> 5;
        const int l    = rt & 31;
        const int half = l >> 4;               // 0: rows (i,g); 1: rows (f,o)
        const int u    = (w << 4) + (l & 15);  // unit 0..63
        const int rA   = half ? (64 + u) : u;          // f : i
        const int rB   = half ? (192 + u) : (128 + u); // o : g

        ull wA[Hh/2], wB[Hh/2];
#pragma unroll
        for (int k = 0; k < Hh/2; k += 2){
            ulonglong2 a = *(const ulonglong2*)&W_hh[rA * Hh + 2*k];
            wA[k] = a.x; wA[k+1] = a.y;
            ulonglong2 c = *(const ulonglong2*)&W_hh[rB * Hh + 2*k];
            wB[k] = c.x; wB[k+1] = c.y;
        }

        // this thread owns states (batch b0+half, u) and (batch b0+half+2, u)
        float c0 = c_init[u], c1 = c_init[u];
        hs[0][half    ][u] = h_init[u];
        hs[0][half + 2][u] = h_init[u];

        float nxA[4], nxB[4];
#pragma unroll
        for (int bb = 0; bb < 4; bb++){
            nxA[bb] = xg_buf[(size_t)(b0 + bb) * 256 + rA];
            nxB[bb] = xg_buf[(size_t)(b0 + bb) * 256 + rB];
        }
        __syncthreads();                       // weights + hs staged

#pragma unroll 1
        for (int t = 0; t < Tt; t++){
            const int pr = t & 1;
            float cuA[4], cuB[4];
#pragma unroll
            for (int bb = 0; bb < 4; bb++){ cuA[bb] = nxA[bb]; cuB[bb] = nxB[bb]; }
            if (t + 1 < Tt){
                size_t base = ((size_t)(t + 1) * Bsz + b0) * 256;
#pragma unroll
                for (int bb = 0; bb < 4; bb++){
                    nxA[bb] = xg_buf[base + (size_t)bb * 256 + rA];
                    nxB[bb] = xg_buf[base + (size_t)bb * 256 + rB];
                }
            }

            ull aAa[4], aAb[4], aBa[4], aBb[4];
#pragma unroll
            for (int bb = 0; bb < 4; bb++){ aAa[bb]=0; aAb[bb]=0; aBa[bb]=0; aBb[bb]=0; }

#pragma unroll
            for (int k = 0; k < Hh; k += 4){
#pragma unroll
                for (int bb = 0; bb < 4; bb++){
                    ulonglong2 v = *(const ulonglong2*)&hs[pr][bb][k];   // broadcast
                    fma2(aAa[bb], wA[k/2    ], v.x);
                    fma2(aAb[bb], wA[k/2 + 1], v.y);
                    fma2(aBa[bb], wB[k/2    ], v.x);
                    fma2(aBb[bb], wB[k/2 + 1], v.y);
                }
            }

            float actA[4], actB[4], pA[4], pB[4];
#pragma unroll
            for (int bb = 0; bb < 4; bb++){
                float2 q0 = unpack2(aAa[bb]), q1 = unpack2(aAb[bb]);
                float gA = cuA[bb] + ((q0.x + q1.x) + (q0.y + q1.y));
                float2 q2 = unpack2(aBa[bb]), q3 = unpack2(aBb[bb]);
                float gB = cuB[bb] + ((q2.x + q3.x) + (q2.y + q3.y));
                actA[bb] = fsigmoid(gA);
                actB[bb] = half ? fsigmoid(gB) : ftanh(gB);
            }
#pragma unroll
            for (int bb = 0; bb < 4; bb++){
                pA[bb] = __shfl_xor_sync(0xffffffffu, actA[bb], 16);
                pB[bb] = __shfl_xor_sync(0xffffffffu, actB[bb], 16);
            }

            // update owned states: bb = half and half+2
#pragma unroll
            for (int o_ = 0; o_ < 2; o_++){
                const int bb = half + 2*o_;
                float ig = half ? pA[bb]   : actA[bb];
                float fg = half ? actA[bb] : pA[bb];
                float gg = half ? pB[bb]   : actB[bb];
                float og = half ? actB[bb] : pB[bb];
                float cold = o_ ? c1 : c0;
                float cn = fmaf(fg, cold, ig * gg);
                if (o_) c1 = cn; else c0 = cn;
                float hn = og * ftanh(cn);
                hs[pr ^ 1][bb][u] = hn;
                y[((size_t)(b0 + bb)) * Tt * Hh + (size_t)t * Hh + u] = hn;
            }

            BAR_REC();                          // rec warps only
            if ((t & 31) == 31) BAR_ALL();      // hand 32-step tile to heads warps
        }
    } else {
        // =================== HEADS (warps 0-3) ===================
        const int bl = tid >> 5;                // batch 0..3
        const int tl = tid & 31;                // t within tile
        __syncthreads();                        // match rec warps' initial sync

#pragma unroll 1
        for (int kblk = 0; kblk < 32; kblk++){
            BAR_ALL();                          // y tile [32*kblk, 32*kblk+32) ready
            const size_t bt = ((size_t)(b0 + bl)) * Tt + (size_t)(kblk * 32 + tl);

            ull yv[Hh/2];
            const ulonglong2* yp = (const ulonglong2*)(y + bt * Hh);
#pragma unroll
            for (int q = 0; q < 16; q++){
                ulonglong2 vv = yp[q];
                yv[2*q] = vv.x; yv[2*q + 1] = vv.y;
            }

#pragma unroll 1
            for (int r = 0; r < Rr; r++){
                ull h1p[MHh/2];
#pragma unroll
                for (int m = 0; m < MHh; m += 2){
                    float hm[2];
#pragma unroll
                    for (int mm = 0; mm < 2; mm++){
                        const ulonglong2* wp = (const ulonglong2*)(W1s + (r*MHh + m + mm) * Hh);
                        ull a0 = 0ULL, a1 = 0ULL, a2 = 0ULL, a3 = 0ULL;
#pragma unroll
                        for (int q = 0; q < 8; q++){
                            ulonglong2 wa = wp[2*q    ];
                            ulonglong2 wb = wp[2*q + 1];
                            fma2(a0, wa.x, yv[4*q    ]);
                            fma2(a1, wa.y, yv[4*q + 1]);
                            fma2(a2, wb.x, yv[4*q + 2]);
                            fma2(a3, wb.y, yv[4*q + 3]);
                        }
                        float2 p0 = unpack2(a0), p1 = unpack2(a1);
                        float2 p2 = unpack2(a2), p3 = unpack2(a3);
                        float s = ((p0.x + p1.x) + (p0.y + p1.y)) + ((p2.x + p3.x) + (p2.y + p3.y));
                        hm[mm] = fmaxf(b1s[r*MHh + m + mm] + s, 0.0f);
                    }
                    h1p[m/2] = pack2(hm[0], hm[1]);
                }

                ull h2p[MHh/2];
#pragma unroll
                for (int n = 0; n < MHh; n += 2){
                    float hv[2];
#pragma unroll
                    for (int nn = 0; nn < 2; nn++){
                        const ulonglong2* wp = (const ulonglong2*)(W2s + (r*MHh + n + nn) * MHh);
                        ull a0 = 0ULL, a1 = 0ULL, a2 = 0ULL, a3 = 0ULL;
#pragma unroll
                        for (int q = 0; q < 4; q++){
                            ulonglong2 wa = wp[2*q    ];
                            ulonglong2 wb = wp[2*q + 1];
                            fma2(a0, wa.x, h1p[4*q    ]);
                            fma2(a1, wa.y, h1p[4*q + 1]);
                            fma2(a2, wb.x, h1p[4*q + 2]);
                            fma2(a3, wb.y, h1p[4*q + 3]);
                        }
                        float2 p0 = unpack2(a0), p1 = unpack2(a1);
                        float2 p2 = unpack2(a2), p3 = unpack2(a3);
                        float s = ((p0.x + p1.x) + (p0.y + p1.y)) + ((p2.x + p3.x) + (p2.y + p3.y));
                        hv[nn] = fmaxf(b2s[r*MHh + n + nn] + s, 0.0f);
                    }
                    h2p[n/2] = pack2(hv[0], hv[1]);
                }

                {
                    const ulonglong2* wp = (const ulonglong2*)(W3s + r * MHh);
                    ull a0 = 0ULL, a1 = 0ULL, a2 = 0ULL, a3 = 0ULL;
#pragma unroll
                    for (int q = 0; q < 4; q++){
                        ulonglong2 wa = wp[2*q    ];
                        ulonglong2 wb = wp[2*q + 1];
                        fma2(a0, wa.x, h2p[4*q    ]);
                        fma2(a1, wa.y, h2p[4*q + 1]);
                        fma2(a2, wb.x, h2p[4*q + 2]);
                        fma2(a3, wb.y, h2p[4*q + 3]);
                    }
                    float2 p0 = unpack2(a0), p1 = unpack2(a1);
                    float2 p2 = unpack2(a2), p3 = unpack2(a3);
                    float s = ((p0.x + p1.x) + (p0.y + p1.y)) + ((p2.x + p3.x) + (p2.y + p3.y));
                    outs[(size_t)r * BT + bt] = b3s[r] + s;
                }
            }
        }
    }
}

extern "C" void kernel_launch(void* const* d_in, const int* in_sizes, int n_in,
                              void* d_out, int out_size)
{
    const float* x      = (const float*)d_in[0];
    const float* h_init = (const float*)d_in[1];
    const float* c_init = (const float*)d_in[2];
    const float* W_ih   = (const float*)d_in[3];
    const float* W_hh   = (const float*)d_in[4];
    const float* b_ih   = (const float*)d_in[5];
    const float* b_hh   = (const float*)d_in[6];
    const float* W1     = (const float*)d_in[7];
    const float* b1     = (const float*)d_in[8];
    const float* W2     = (const float*)d_in[9];
    const float* b2     = (const float*)d_in[10];
    const float* W3     = (const float*)d_in[11];
    const float* b3     = (const float*)d_in[12];

    float* y    = (float*)d_out;                     // (B, T, H)
    float* outs = y + (size_t)Bsz * Tt * Hh;         // (R, B, T)

    proj_kernel<<<Bsz * 4, 128>>>(x, W_ih, b_ih, b_hh);

    const size_t shmem = 12688 * sizeof(float);      // 50752 B
    cudaFuncSetAttribute(fused_kernel,
                         cudaFuncAttributeMaxDynamicSharedMemorySize, (int)shmem);
    fused_kernel<<<Bsz / 4, 256, shmem>>>(h_init, c_init, W_hh,
                                          W1, b1, W2, b2, W3, b3, y, outs);
}

// round 15
// speedup vs baseline: 1.4564x; 1.0769x over previous
#include <cuda_runtime.h>
#include <math.h>

#define Bsz 512
#define Tt  1024
#define Dd  64
#define Hh  64
#define Rr  4
#define MHh 32
#define PCH 16

typedef unsigned long long ull;

// xg scratch, plain row order: xg[t][b][row], bias baked in. 512MB.
__device__ float xg_buf[(size_t)Tt * Bsz * 256];

// Heads weights in constant memory: warp-uniform reads -> LDC/LDCU path,
// zero L1/LDS pressure. Total 49.2KB < 64KB bank.
__constant__ float cW1[Rr*MHh*Hh];   // 8192
__constant__ float cW2[Rr*MHh*MHh];  // 4096
__constant__ float cW3[Rr*MHh];      // 128
__constant__ float cb1[Rr*MHh];      // 128
__constant__ float cb2[Rr*MHh];      // 128
__constant__ float cb3[Rr];          // 4

__device__ __forceinline__ void fma2(ull &d, ull a, ull b){
    asm("fma.rn.f32x2 %0, %1, %2, %0;" : "+l"(d) : "l"(a), "l"(b));
}
__device__ __forceinline__ ull pack2(float lo, float hi){
    ull r; asm("mov.b64 %0, {%1, %2};" : "=l"(r) : "f"(lo), "f"(hi)); return r;
}
__device__ __forceinline__ float2 unpack2(ull v){
    float2 r; asm("mov.b64 {%0, %1}, %2;" : "=f"(r.x), "=f"(r.y) : "l"(v)); return r;
}

__device__ __forceinline__ float fsigmoid(float v){
    float e = __expf(-v);
    return __fdividef(1.0f, 1.0f + e);
}
// Saturation-safe: exp argument always <= 0.
__device__ __forceinline__ float ftanh(float v){
    float t = __expf(-2.0f * fabsf(v));
    float r = __fdividef(1.0f - t, 1.0f + t);
    return copysignf(r, v);
}

// ---------------------------------------------------------------------------
// Input projection (round-12 exact, double-buffered).
// ---------------------------------------------------------------------------
__global__ __launch_bounds__(128)
void proj_kernel(const float* __restrict__ x,
                 const float* __restrict__ W_ih,
                 const float* __restrict__ b_ih,
                 const float* __restrict__ b_hh)
{
    const int j  = threadIdx.x;
    const int r0 = 2*j, r1 = 2*j + 1;
    const int b  = blockIdx.x >> 2;
    const int t0 = (blockIdx.x & 3) * 256;

    __shared__ __align__(16) float xsh[2][PCH][Dd];

    ull w0[Dd/2], w1[Dd/2];
#pragma unroll
    for (int k = 0; k < Dd/2; k += 2){
        ulonglong2 a = *(const ulonglong2*)&W_ih[r0 * Dd + 2*k];
        w0[k] = a.x; w0[k+1] = a.y;
        ulonglong2 c = *(const ulonglong2*)&W_ih[r1 * Dd + 2*k];
        w1[k] = c.x; w1[k+1] = c.y;
    }
    const float bj0 = b_ih[r0] + b_hh[r0];
    const float bj1 = b_ih[r1] + b_hh[r1];

    const float4* xbase = (const float4*)(x + ((size_t)b * Tt + t0) * Dd);
    const int CHUNK4 = PCH * Dd / 4;

    {
        float4 pa = xbase[j], pb = xbase[j + 128];
        float4* dst = (float4*)&xsh[0][0][0];
        dst[j] = pa; dst[j + 128] = pb;
    }
    __syncthreads();

    for (int c = 0; c < 256 / PCH; c++){
        const int pb_ = c & 1;
        float4 pa, pbv;
        if (c + 1 < 256 / PCH){
            const float4* src = xbase + (size_t)(c + 1) * CHUNK4;
            pa  = src[j];
            pbv = src[j + 128];
        }

#pragma unroll 4
        for (int p = 0; p < PCH; p++){
            const ulonglong2* v = (const ulonglong2*)&xsh[pb_][p][0];
            ull a00 = 0ULL, a01 = 0ULL, a10 = 0ULL, a11 = 0ULL;
#pragma unroll
            for (int q = 0; q < 16; q++){
                ulonglong2 xx = v[q];
                fma2(a00, w0[2*q    ], xx.x);
                fma2(a01, w0[2*q + 1], xx.y);
                fma2(a10, w1[2*q    ], xx.x);
                fma2(a11, w1[2*q + 1], xx.y);
            }
            float2 p0 = unpack2(a00), p1 = unpack2(a01);
            float2 p2 = unpack2(a10), p3 = unpack2(a11);
            size_t base = ((size_t)(t0 + c * PCH + p) * Bsz + b) * 256;
            float2 o;
            o.x = bj0 + ((p0.x + p1.x) + (p0.y + p1.y));
            o.y = bj1 + ((p2.x + p3.x) + (p2.y + p3.y));
            *(float2*)&xg_buf[base + 2*j] = o;
        }

        if (c + 1 < 256 / PCH){
            float4* dst = (float4*)&xsh[pb_ ^ 1][0][0];
            dst[j] = pa; dst[j + 128] = pbv;
        }
        __syncthreads();
    }
}

// ---------------------------------------------------------------------------
// Recurrence v3 (round-12 exact — best measured ~650us).
// ---------------------------------------------------------------------------
__global__ __launch_bounds__(128, 2)
void lstm_rec_kernel(const float* __restrict__ h_init,
                     const float* __restrict__ c_init,
                     const float* __restrict__ W_hh,
                     float* __restrict__ y)
{
    const int tid  = threadIdx.x;
    const int w    = tid >> 5;
    const int l    = tid & 31;
    const int half = l >> 4;
    const int u    = (w << 4) + (l & 15);
    const int rA   = half ? (64 + u) : u;
    const int rB   = half ? (192 + u) : (128 + u);
    const int b0   = blockIdx.x * 2;

    __shared__ __align__(16) float hs[2][2][Hh];

    ull wA[Hh/2], wB[Hh/2];
#pragma unroll
    for (int k = 0; k < Hh/2; k += 2){
        ulonglong2 a = *(const ulonglong2*)&W_hh[rA * Hh + 2*k];
        wA[k] = a.x; wA[k+1] = a.y;
        ulonglong2 c = *(const ulonglong2*)&W_hh[rB * Hh + 2*k];
        wB[k] = c.x; wB[k+1] = c.y;
    }

    float creg = c_init[u];
    hs[0][half][u] = h_init[u];

    float xA0 = xg_buf[(size_t)(b0    ) * 256 + rA];
    float xB0 = xg_buf[(size_t)(b0    ) * 256 + rB];
    float xA1 = xg_buf[(size_t)(b0 + 1) * 256 + rA];
    float xB1 = xg_buf[(size_t)(b0 + 1) * 256 + rB];
    __syncthreads();

#pragma unroll 1
    for (int t = 0; t < Tt; t++){
        const int pr = t & 1;
        float cA0 = xA0, cB0 = xB0, cA1 = xA1, cB1 = xB1;
        if (t + 1 < Tt){
            size_t base = ((size_t)(t + 1) * Bsz + b0) * 256;
            xA0 = xg_buf[base + rA];
            xB0 = xg_buf[base + rB];
            xA1 = xg_buf[base + 256 + rA];
            xB1 = xg_buf[base + 256 + rB];
        }

        ull aA0a=0,aA0b=0,aB0a=0,aB0b=0,aA1a=0,aA1b=0,aB1a=0,aB1b=0;
#pragma unroll
        for (int k = 0; k < Hh; k += 4){
            ulonglong2 v0 = *(const ulonglong2*)&hs[pr][0][k];
            ulonglong2 v1 = *(const ulonglong2*)&hs[pr][1][k];
            fma2(aA0a, wA[k/2    ], v0.x);
            fma2(aA0b, wA[k/2 + 1], v0.y);
            fma2(aB0a, wB[k/2    ], v0.x);
            fma2(aB0b, wB[k/2 + 1], v0.y);
            fma2(aA1a, wA[k/2    ], v1.x);
            fma2(aA1b, wA[k/2 + 1], v1.y);
            fma2(aB1a, wB[k/2    ], v1.x);
            fma2(aB1b, wB[k/2 + 1], v1.y);
        }
        float2 q0, q1;
        q0 = unpack2(aA0a); q1 = unpack2(aA0b);
        float gA0 = cA0 + ((q0.x + q1.x) + (q0.y + q1.y));
        q0 = unpack2(aB0a); q1 = unpack2(aB0b);
        float gB0 = cB0 + ((q0.x + q1.x) + (q0.y + q1.y));
        q0 = unpack2(aA1a); q1 = unpack2(aA1b);
        float gA1 = cA1 + ((q0.x + q1.x) + (q0.y + q1.y));
        q0 = unpack2(aB1a); q1 = unpack2(aB1b);
        float gB1 = cB1 + ((q0.x + q1.x) + (q0.y + q1.y));

        float aA0 = fsigmoid(gA0);
        float aA1 = fsigmoid(gA1);
        float aB0 = half ? fsigmoid(gB0) : ftanh(gB0);
        float aB1 = half ? fsigmoid(gB1) : ftanh(gB1);

        float pA0 = __shfl_xor_sync(0xffffffffu, aA0, 16);
        float pB0 = __shfl_xor_sync(0xffffffffu, aB0, 16);
        float pA1 = __shfl_xor_sync(0xffffffffu, aA1, 16);
        float pB1 = __shfl_xor_sync(0xffffffffu, aB1, 16);

        float ig = half ? pA1 : aA0;
        float fg = half ? aA1 : pA0;
        float gg = half ? pB1 : aB0;
        float og = half ? aB1 : pB0;

        float cn = fmaf(fg, creg, ig * gg);
        creg = cn;
        float hn = og * ftanh(cn);
        hs[pr ^ 1][half][u] = hn;
        y[((size_t)(b0 + half)) * Tt * Hh + (size_t)t * Hh + u] = hn;

        __syncthreads();
    }
}

// ---------------------------------------------------------------------------
// Heads v4: weights from CONSTANT memory (warp-uniform -> LDC path, no L1
// pressure). Only y goes through shared. Same verified dot-product math.
// ---------------------------------------------------------------------------
__global__ __launch_bounds__(128, 4)
void heads_kernel(const float* __restrict__ y, float* __restrict__ outs)
{
    __shared__ ull ysp[32 * 129];    // packed y tile, 33024 B

    const int tid    = threadIdx.x;
    const size_t bt0 = (size_t)blockIdx.x * 128;
    const size_t BT  = (size_t)Bsz * Tt;

    {
        const float4* ysrc = (const float4*)(y + bt0 * Hh);
#pragma unroll
        for (int it = 0; it < 16; it++){
            int i4  = tid + it * 128;
            float4 v = ysrc[i4];
            int bt = i4 >> 4;
            int k2 = (i4 & 15) * 2;
            ysp[(k2    ) * 129 + bt] = pack2(v.x, v.y);
            ysp[(k2 + 1) * 129 + bt] = pack2(v.z, v.w);
        }
    }
    __syncthreads();

    ull yv[Hh/2];
#pragma unroll
    for (int k = 0; k < Hh/2; k++) yv[k] = ysp[k * 129 + tid];

#pragma unroll 1
    for (int r = 0; r < Rr; r++){
        ull h1p[MHh/2];
#pragma unroll
        for (int m = 0; m < MHh; m += 2){
            float hm[2];
#pragma unroll
            for (int mm = 0; mm < 2; mm++){
                const ulonglong2* wp = (const ulonglong2*)(cW1 + (r*MHh + m + mm) * Hh);
                ull a0 = 0ULL, a1 = 0ULL, a2 = 0ULL, a3 = 0ULL;
#pragma unroll
                for (int q = 0; q < 8; q++){
                    ulonglong2 wa = wp[2*q    ];     // uniform -> LDC
                    ulonglong2 wb = wp[2*q + 1];
                    fma2(a0, wa.x, yv[4*q    ]);
                    fma2(a1, wa.y, yv[4*q + 1]);
                    fma2(a2, wb.x, yv[4*q + 2]);
                    fma2(a3, wb.y, yv[4*q + 3]);
                }
                float2 p0 = unpack2(a0), p1 = unpack2(a1);
                float2 p2 = unpack2(a2), p3 = unpack2(a3);
                float s = ((p0.x + p1.x) + (p0.y + p1.y)) + ((p2.x + p3.x) + (p2.y + p3.y));
                hm[mm] = fmaxf(cb1[r*MHh + m + mm] + s, 0.0f);
            }
            h1p[m/2] = pack2(hm[0], hm[1]);
        }

        ull h2p[MHh/2];
#pragma unroll
        for (int n = 0; n < MHh; n += 2){
            float hv[2];
#pragma unroll
            for (int nn = 0; nn < 2; nn++){
                const ulonglong2* wp = (const ulonglong2*)(cW2 + (r*MHh + n + nn) * MHh);
                ull a0 = 0ULL, a1 = 0ULL, a2 = 0ULL, a3 = 0ULL;
#pragma unroll
                for (int q = 0; q < 4; q++){
                    ulonglong2 wa = wp[2*q    ];
                    ulonglong2 wb = wp[2*q + 1];
                    fma2(a0, wa.x, h1p[4*q    ]);
                    fma2(a1, wa.y, h1p[4*q + 1]);
                    fma2(a2, wb.x, h1p[4*q + 2]);
                    fma2(a3, wb.y, h1p[4*q + 3]);
                }
                float2 p0 = unpack2(a0), p1 = unpack2(a1);
                float2 p2 = unpack2(a2), p3 = unpack2(a3);
                float s = ((p0.x + p1.x) + (p0.y + p1.y)) + ((p2.x + p3.x) + (p2.y + p3.y));
                hv[nn] = fmaxf(cb2[r*MHh + n + nn] + s, 0.0f);
            }
            h2p[n/2] = pack2(hv[0], hv[1]);
        }

        {
            const ulonglong2* wp = (const ulonglong2*)(cW3 + r * MHh);
            ull a0 = 0ULL, a1 = 0ULL, a2 = 0ULL, a3 = 0ULL;
#pragma unroll
            for (int q = 0; q < 4; q++){
                ulonglong2 wa = wp[2*q    ];
                ulonglong2 wb = wp[2*q + 1];
                fma2(a0, wa.x, h2p[4*q    ]);
                fma2(a1, wa.y, h2p[4*q + 1]);
                fma2(a2, wb.x, h2p[4*q + 2]);
                fma2(a3, wb.y, h2p[4*q + 3]);
            }
            float2 p0 = unpack2(a0), p1 = unpack2(a1);
            float2 p2 = unpack2(a2), p3 = unpack2(a3);
            float s = ((p0.x + p1.x) + (p0.y + p1.y)) + ((p2.x + p3.x) + (p2.y + p3.y));
            outs[(size_t)r * BT + bt0 + tid] = cb3[r] + s;
        }
    }
}

extern "C" void kernel_launch(void* const* d_in, const int* in_sizes, int n_in,
                              void* d_out, int out_size)
{
    const float* x      = (const float*)d_in[0];
    const float* h_init = (const float*)d_in[1];
    const float* c_init = (const float*)d_in[2];
    const float* W_ih   = (const float*)d_in[3];
    const float* W_hh   = (const float*)d_in[4];
    const float* b_ih   = (const float*)d_in[5];
    const float* b_hh   = (const float*)d_in[6];
    const float* W1     = (const float*)d_in[7];
    const float* b1     = (const float*)d_in[8];
    const float* W2     = (const float*)d_in[9];
    const float* b2     = (const float*)d_in[10];
    const float* W3     = (const float*)d_in[11];
    const float* b3     = (const float*)d_in[12];

    float* y    = (float*)d_out;                     // (B, T, H)
    float* outs = y + (size_t)Bsz * Tt * Hh;         // (R, B, T)

    // copy heads weights into constant bank (D2D async memcpy, capturable)
    cudaMemcpyToSymbolAsync(cW1, W1, Rr*MHh*Hh  * sizeof(float), 0, cudaMemcpyDeviceToDevice);
    cudaMemcpyToSymbolAsync(cW2, W2, Rr*MHh*MHh * sizeof(float), 0, cudaMemcpyDeviceToDevice);
    cudaMemcpyToSymbolAsync(cW3, W3, Rr*MHh     * sizeof(float), 0, cudaMemcpyDeviceToDevice);
    cudaMemcpyToSymbolAsync(cb1, b1, Rr*MHh     * sizeof(float), 0, cudaMemcpyDeviceToDevice);
    cudaMemcpyToSymbolAsync(cb2, b2, Rr*MHh     * sizeof(float), 0, cudaMemcpyDeviceToDevice);
    cudaMemcpyToSymbolAsync(cb3, b3, Rr         * sizeof(float), 0, cudaMemcpyDeviceToDevice);

    proj_kernel<<<Bsz * 4, 128>>>(x, W_ih, b_ih, b_hh);

    lstm_rec_kernel<<<Bsz / 2, 128>>>(h_init, c_init, W_hh, y);

    heads_kernel<<<(Bsz * Tt) / 128, 128>>>(y, outs);
}

// round 16
// speedup vs baseline: 1.5860x; 1.0890x over previous
#include <cuda_runtime.h>
#include <math.h>

#define Bsz 512
#define Tt  1024
#define Dd  64
#define Hh  64
#define Rr  4
#define MHh 32
#define PCH 16
#define NREC 256

typedef unsigned long long ull;

// xg scratch, plain row order: xg[t][b][row], bias baked in. 512MB.
__device__ float xg_buf[(size_t)Tt * Bsz * 256];
// per-rec-block progress (steps completed); zeroed by proj_kernel each launch
__device__ unsigned prog_flag[NREC];

__device__ __forceinline__ void fma2(ull &d, ull a, ull b){
    asm("fma.rn.f32x2 %0, %1, %2, %0;" : "+l"(d) : "l"(a), "l"(b));
}
__device__ __forceinline__ ull pack2(float lo, float hi){
    ull r; asm("mov.b64 %0, {%1, %2};" : "=l"(r) : "f"(lo), "f"(hi)); return r;
}
__device__ __forceinline__ float2 unpack2(ull v){
    float2 r; asm("mov.b64 {%0, %1}, %2;" : "=f"(r.x), "=f"(r.y) : "l"(v)); return r;
}

__device__ __forceinline__ float fsigmoid(float v){
    float e = __expf(-v);
    return __fdividef(1.0f, 1.0f + e);
}
// Saturation-safe: exp argument always <= 0.
__device__ __forceinline__ float ftanh(float v){
    float t = __expf(-2.0f * fabsf(v));
    float r = __fdividef(1.0f - t, 1.0f + t);
    return copysignf(r, v);
}

// ---------------------------------------------------------------------------
// Input projection (round-12 exact, double-buffered). First 256 blocks also
// zero the progress flags (visible to the next kernel via stream order).
// ---------------------------------------------------------------------------
__global__ __launch_bounds__(128)
void proj_kernel(const float* __restrict__ x,
                 const float* __restrict__ W_ih,
                 const float* __restrict__ b_ih,
                 const float* __restrict__ b_hh)
{
    const int j  = threadIdx.x;
    if (j == 0 && blockIdx.x < NREC) prog_flag[blockIdx.x] = 0u;

    const int r0 = 2*j, r1 = 2*j + 1;
    const int b  = blockIdx.x >> 2;
    const int t0 = (blockIdx.x & 3) * 256;

    __shared__ __align__(16) float xsh[2][PCH][Dd];

    ull w0[Dd/2], w1[Dd/2];
#pragma unroll
    for (int k = 0; k < Dd/2; k += 2){
        ulonglong2 a = *(const ulonglong2*)&W_ih[r0 * Dd + 2*k];
        w0[k] = a.x; w0[k+1] = a.y;
        ulonglong2 c = *(const ulonglong2*)&W_ih[r1 * Dd + 2*k];
        w1[k] = c.x; w1[k+1] = c.y;
    }
    const float bj0 = b_ih[r0] + b_hh[r0];
    const float bj1 = b_ih[r1] + b_hh[r1];

    const float4* xbase = (const float4*)(x + ((size_t)b * Tt + t0) * Dd);
    const int CHUNK4 = PCH * Dd / 4;

    {
        float4 pa = xbase[j], pb = xbase[j + 128];
        float4* dst = (float4*)&xsh[0][0][0];
        dst[j] = pa; dst[j + 128] = pb;
    }
    __syncthreads();

    for (int c = 0; c < 256 / PCH; c++){
        const int pb_ = c & 1;
        float4 pa, pbv;
        if (c + 1 < 256 / PCH){
            const float4* src = xbase + (size_t)(c + 1) * CHUNK4;
            pa  = src[j];
            pbv = src[j + 128];
        }

#pragma unroll 4
        for (int p = 0; p < PCH; p++){
            const ulonglong2* v = (const ulonglong2*)&xsh[pb_][p][0];
            ull a00 = 0ULL, a01 = 0ULL, a10 = 0ULL, a11 = 0ULL;
#pragma unroll
            for (int q = 0; q < 16; q++){
                ulonglong2 xx = v[q];
                fma2(a00, w0[2*q    ], xx.x);
                fma2(a01, w0[2*q + 1], xx.y);
                fma2(a10, w1[2*q    ], xx.x);
                fma2(a11, w1[2*q + 1], xx.y);
            }
            float2 p0 = unpack2(a00), p1 = unpack2(a01);
            float2 p2 = unpack2(a10), p3 = unpack2(a11);
            size_t base = ((size_t)(t0 + c * PCH + p) * Bsz + b) * 256;
            float2 o;
            o.x = bj0 + ((p0.x + p1.x) + (p0.y + p1.y));
            o.y = bj1 + ((p2.x + p3.x) + (p2.y + p3.y));
            *(float2*)&xg_buf[base + 2*j] = o;
        }

        if (c + 1 < 256 / PCH){
            float4* dst = (float4*)&xsh[pb_ ^ 1][0][0];
            dst[j] = pa; dst[j + 128] = pbv;
        }
        __syncthreads();
    }
}

// ---------------------------------------------------------------------------
// Combined rec+heads kernel, block-specialized.
// Blocks [0,256): round-12 v3 recurrence (2 batches) + progress publication
//   every 64 steps (threadfence-reduction idiom).
// Blocks [256,4352): round-12 heads for one 128-point tile; spin-waits
//   (ld.acquire + nanosleep) until its batch's rec progress covers the tile.
// In-order dispatch places all rec blocks first -> deadlock-free.
// ---------------------------------------------------------------------------
__global__ __launch_bounds__(128, 3)
void combo_kernel(const float* __restrict__ h_init,
                  const float* __restrict__ c_init,
                  const float* __restrict__ W_hh,
                  const float* __restrict__ W1, const float* __restrict__ b1,
                  const float* __restrict__ W2, const float* __restrict__ b2,
                  const float* __restrict__ W3, const float* __restrict__ b3,
                  float* y, float* __restrict__ outs)
{
    extern __shared__ float sm[];
    const int tid = threadIdx.x;
    const size_t BT = (size_t)Bsz * Tt;

    if (blockIdx.x < NREC){
        // ===================== RECURRENCE (round-12 v3) =====================
        __shared__ __align__(16) float hs[2][2][Hh];
        const int w    = tid >> 5;
        const int l    = tid & 31;
        const int half = l >> 4;
        const int u    = (w << 4) + (l & 15);
        const int rA   = half ? (64 + u) : u;
        const int rB   = half ? (192 + u) : (128 + u);
        const int b0   = blockIdx.x * 2;

        ull wA[Hh/2], wB[Hh/2];
#pragma unroll
        for (int k = 0; k < Hh/2; k += 2){
            ulonglong2 a = *(const ulonglong2*)&W_hh[rA * Hh + 2*k];
            wA[k] = a.x; wA[k+1] = a.y;
            ulonglong2 c = *(const ulonglong2*)&W_hh[rB * Hh + 2*k];
            wB[k] = c.x; wB[k+1] = c.y;
        }

        float creg = c_init[u];
        hs[0][half][u] = h_init[u];

        float xA0 = xg_buf[(size_t)(b0    ) * 256 + rA];
        float xB0 = xg_buf[(size_t)(b0    ) * 256 + rB];
        float xA1 = xg_buf[(size_t)(b0 + 1) * 256 + rA];
        float xB1 = xg_buf[(size_t)(b0 + 1) * 256 + rB];
        __syncthreads();

#pragma unroll 1
        for (int t = 0; t < Tt; t++){
            const int pr = t & 1;
            float cA0 = xA0, cB0 = xB0, cA1 = xA1, cB1 = xB1;
            if (t + 1 < Tt){
                size_t base = ((size_t)(t + 1) * Bsz + b0) * 256;
                xA0 = xg_buf[base + rA];
                xB0 = xg_buf[base + rB];
                xA1 = xg_buf[base + 256 + rA];
                xB1 = xg_buf[base + 256 + rB];
            }

            ull aA0a=0,aA0b=0,aB0a=0,aB0b=0,aA1a=0,aA1b=0,aB1a=0,aB1b=0;
#pragma unroll
            for (int k = 0; k < Hh; k += 4){
                ulonglong2 v0 = *(const ulonglong2*)&hs[pr][0][k];
                ulonglong2 v1 = *(const ulonglong2*)&hs[pr][1][k];
                fma2(aA0a, wA[k/2    ], v0.x);
                fma2(aA0b, wA[k/2 + 1], v0.y);
                fma2(aB0a, wB[k/2    ], v0.x);
                fma2(aB0b, wB[k/2 + 1], v0.y);
                fma2(aA1a, wA[k/2    ], v1.x);
                fma2(aA1b, wA[k/2 + 1], v1.y);
                fma2(aB1a, wB[k/2    ], v1.x);
                fma2(aB1b, wB[k/2 + 1], v1.y);
            }
            float2 q0, q1;
            q0 = unpack2(aA0a); q1 = unpack2(aA0b);
            float gA0 = cA0 + ((q0.x + q1.x) + (q0.y + q1.y));
            q0 = unpack2(aB0a); q1 = unpack2(aB0b);
            float gB0 = cB0 + ((q0.x + q1.x) + (q0.y + q1.y));
            q0 = unpack2(aA1a); q1 = unpack2(aA1b);
            float gA1 = cA1 + ((q0.x + q1.x) + (q0.y + q1.y));
            q0 = unpack2(aB1a); q1 = unpack2(aB1b);
            float gB1 = cB1 + ((q0.x + q1.x) + (q0.y + q1.y));

            float aA0 = fsigmoid(gA0);
            float aA1 = fsigmoid(gA1);
            float aB0 = half ? fsigmoid(gB0) : ftanh(gB0);
            float aB1 = half ? fsigmoid(gB1) : ftanh(gB1);

            float pA0 = __shfl_xor_sync(0xffffffffu, aA0, 16);
            float pB0 = __shfl_xor_sync(0xffffffffu, aB0, 16);
            float pA1 = __shfl_xor_sync(0xffffffffu, aA1, 16);
            float pB1 = __shfl_xor_sync(0xffffffffu, aB1, 16);

            float ig = half ? pA1 : aA0;
            float fg = half ? aA1 : pA0;
            float gg = half ? pB1 : aB0;
            float og = half ? aB1 : pB0;

            float cn = fmaf(fg, creg, ig * gg);
            creg = cn;
            float hn = og * ftanh(cn);
            hs[pr ^ 1][half][u] = hn;
            y[((size_t)(b0 + half)) * Tt * Hh + (size_t)t * Hh + u] = hn;

            if ((t & 63) == 63) __threadfence();   // make y visible GPU-wide
            __syncthreads();
            if ((t & 63) == 63 && tid == 0)
                atomicExch(&prog_flag[blockIdx.x], (unsigned)(t + 1));
        }
    } else {
        // ========================= HEADS (round-12) =========================
        float* w1r = sm;                 // 2048
        float* w2r = w1r + 2048;         // 1024
        float* w3r = w2r + 1024;         // 32
        float* b1r = w3r + 32;           // 32
        float* b2r = b1r + 32;           // 32
        float* b3r = b2r + 32;           // pad 8
        ull*   ysp = (ull*)(sm + 3200);  // [32][129] ull

        const int hb  = blockIdx.x - NREC;
        const int b   = hb & (Bsz - 1);
        const int tl0 = (hb >> 9) * 128;            // t-ascending tiles
        const size_t bt0 = (size_t)b * Tt + tl0;

        // wait for rec progress to cover this tile
        if (tid == 0){
            const unsigned need = (unsigned)(tl0 + 128);
            unsigned v;
            while (true){
                asm volatile("ld.acquire.gpu.global.u32 %0, [%1];"
                             : "=r"(v) : "l"(&prog_flag[b >> 1]) : "memory");
                if (v >= need) break;
                __nanosleep(256);
            }
        }
        __syncthreads();

        {
            const float4* ysrc = (const float4*)(y + bt0 * Hh);
#pragma unroll
            for (int it = 0; it < 16; it++){
                int i4  = tid + it * 128;
                float4 v = ysrc[i4];
                int bt = i4 >> 4;
                int k2 = (i4 & 15) * 2;
                ysp[(k2    ) * 129 + bt] = pack2(v.x, v.y);
                ysp[(k2 + 1) * 129 + bt] = pack2(v.z, v.w);
            }
        }

#pragma unroll 1
        for (int r = 0; r < Rr; r++){
            __syncthreads();
            {
                const float4* s1 = (const float4*)(W1 + r * 2048);
                float4* d1 = (float4*)w1r;
                d1[tid] = s1[tid]; d1[tid+128] = s1[tid+128];
                d1[tid+256] = s1[tid+256]; d1[tid+384] = s1[tid+384];
                const float4* s2 = (const float4*)(W2 + r * 1024);
                float4* d2 = (float4*)w2r;
                d2[tid] = s2[tid]; d2[tid+128] = s2[tid+128];
                if (tid < 8) ((float4*)w3r)[tid] = ((const float4*)(W3 + r * 32))[tid];
                if (tid < 32){ b1r[tid] = b1[r*32 + tid]; b2r[tid] = b2[r*32 + tid]; }
                if (tid == 0) b3r[0] = b3[r];
            }
            __syncthreads();

            ull yv[Hh/2];
#pragma unroll
            for (int k = 0; k < Hh/2; k++) yv[k] = ysp[k * 129 + tid];

            ull h1p[MHh/2];
#pragma unroll
            for (int m = 0; m < MHh; m += 2){
                float hm[2];
#pragma unroll
                for (int mm = 0; mm < 2; mm++){
                    const ulonglong2* wp = (const ulonglong2*)(w1r + (m + mm) * Hh);
                    ull a0 = 0ULL, a1 = 0ULL, a2 = 0ULL, a3 = 0ULL;
#pragma unroll
                    for (int q = 0; q < 8; q++){
                        ulonglong2 wa = wp[2*q    ];
                        ulonglong2 wb = wp[2*q + 1];
                        fma2(a0, wa.x, yv[4*q    ]);
                        fma2(a1, wa.y, yv[4*q + 1]);
                        fma2(a2, wb.x, yv[4*q + 2]);
                        fma2(a3, wb.y, yv[4*q + 3]);
                    }
                    float2 p0 = unpack2(a0), p1 = unpack2(a1);
                    float2 p2 = unpack2(a2), p3 = unpack2(a3);
                    float s = ((p0.x + p1.x) + (p0.y + p1.y)) + ((p2.x + p3.x) + (p2.y + p3.y));
                    hm[mm] = fmaxf(b1r[m + mm] + s, 0.0f);
                }
                h1p[m/2] = pack2(hm[0], hm[1]);
            }

            ull h2p[MHh/2];
#pragma unroll
            for (int n = 0; n < MHh; n += 2){
                float hv[2];
#pragma unroll
                for (int nn = 0; nn < 2; nn++){
                    const ulonglong2* wp = (const ulonglong2*)(w2r + (n + nn) * MHh);
                    ull a0 = 0ULL, a1 = 0ULL, a2 = 0ULL, a3 = 0ULL;
#pragma unroll
                    for (int q = 0; q < 4; q++){
                        ulonglong2 wa = wp[2*q    ];
                        ulonglong2 wb = wp[2*q + 1];
                        fma2(a0, wa.x, h1p[4*q    ]);
                        fma2(a1, wa.y, h1p[4*q + 1]);
                        fma2(a2, wb.x, h1p[4*q + 2]);
                        fma2(a3, wb.y, h1p[4*q + 3]);
                    }
                    float2 p0 = unpack2(a0), p1 = unpack2(a1);
                    float2 p2 = unpack2(a2), p3 = unpack2(a3);
                    float s = ((p0.x + p1.x) + (p0.y + p1.y)) + ((p2.x + p3.x) + (p2.y + p3.y));
                    hv[nn] = fmaxf(b2r[n + nn] + s, 0.0f);
                }
                h2p[n/2] = pack2(hv[0], hv[1]);
            }

            {
                const ulonglong2* wp = (const ulonglong2*)w3r;
                ull a0 = 0ULL, a1 = 0ULL, a2 = 0ULL, a3 = 0ULL;
#pragma unroll
                for (int q = 0; q < 4; q++){
                    ulonglong2 wa = wp[2*q    ];
                    ulonglong2 wb = wp[2*q + 1];
                    fma2(a0, wa.x, h2p[4*q    ]);
                    fma2(a1, wa.y, h2p[4*q + 1]);
                    fma2(a2, wb.x, h2p[4*q + 2]);
                    fma2(a3, wb.y, h2p[4*q + 3]);
                }
                float2 p0 = unpack2(a0), p1 = unpack2(a1);
                float2 p2 = unpack2(a2), p3 = unpack2(a3);
                float s = ((p0.x + p1.x) + (p0.y + p1.y)) + ((p2.x + p3.x) + (p2.y + p3.y));
                outs[(size_t)r * BT + bt0 + tid] = b3r[0] + s;
            }
        }
    }
}

extern "C" void kernel_launch(void* const* d_in, const int* in_sizes, int n_in,
                              void* d_out, int out_size)
{
    const float* x      = (const float*)d_in[0];
    const float* h_init = (const float*)d_in[1];
    const float* c_init = (const float*)d_in[2];
    const float* W_ih   = (const float*)d_in[3];
    const float* W_hh   = (const float*)d_in[4];
    const float* b_ih   = (const float*)d_in[5];
    const float* b_hh   = (const float*)d_in[6];
    const float* W1     = (const float*)d_in[7];
    const float* b1     = (const float*)d_in[8];
    const float* W2     = (const float*)d_in[9];
    const float* b2     = (const float*)d_in[10];
    const float* W3     = (const float*)d_in[11];
    const float* b3     = (const float*)d_in[12];

    float* y    = (float*)d_out;                     // (B, T, H)
    float* outs = y + (size_t)Bsz * Tt * Hh;         // (R, B, T)

    proj_kernel<<<Bsz * 4, 128>>>(x, W_ih, b_ih, b_hh);

    const size_t shmem = 3200 * sizeof(float) + 32 * 129 * sizeof(ull);  // 45824 B
    combo_kernel<<<NREC + (Bsz * Tt) / 128, 128, shmem>>>(
        h_init, c_init, W_hh, W1, b1, W2, b2, W3, b3, y, outs);
}

// round 17
// speedup vs baseline: 1.6983x; 1.0708x over previous
#include <cuda_runtime.h>
#include <math.h>

#define Bsz 512
#define Tt  1024
#define Dd  64
#define Hh  64
#define Rr  4
#define MHh 32
#define PCH 16

typedef unsigned long long ull;

// xg scratch, plain row order: xg[t][b][row], bias baked in. 512MB.
__device__ float xg_buf[(size_t)Tt * Bsz * 256];

__device__ __forceinline__ void fma2(ull &d, ull a, ull b){
    asm("fma.rn.f32x2 %0, %1, %2, %0;" : "+l"(d) : "l"(a), "l"(b));
}
__device__ __forceinline__ ull pack2(float lo, float hi){
    ull r; asm("mov.b64 %0, {%1, %2};" : "=l"(r) : "f"(lo), "f"(hi)); return r;
}
__device__ __forceinline__ float2 unpack2(ull v){
    float2 r; asm("mov.b64 {%0, %1}, %2;" : "=f"(r.x), "=f"(r.y) : "l"(v)); return r;
}

__device__ __forceinline__ float fsigmoid(float v){
    float e = __expf(-v);
    return __fdividef(1.0f, 1.0f + e);
}
// Saturation-safe: exp argument always <= 0.
__device__ __forceinline__ float ftanh(float v){
    float t = __expf(-2.0f * fabsf(v));
    float r = __fdividef(1.0f - t, 1.0f + t);
    return copysignf(r, v);
}

// ---------------------------------------------------------------------------
// Input projection (round-12 exact, double-buffered).
// ---------------------------------------------------------------------------
__global__ __launch_bounds__(128)
void proj_kernel(const float* __restrict__ x,
                 const float* __restrict__ W_ih,
                 const float* __restrict__ b_ih,
                 const float* __restrict__ b_hh)
{
    const int j  = threadIdx.x;
    const int r0 = 2*j, r1 = 2*j + 1;
    const int b  = blockIdx.x >> 2;
    const int t0 = (blockIdx.x & 3) * 256;

    __shared__ __align__(16) float xsh[2][PCH][Dd];

    ull w0[Dd/2], w1[Dd/2];
#pragma unroll
    for (int k = 0; k < Dd/2; k += 2){
        ulonglong2 a = *(const ulonglong2*)&W_ih[r0 * Dd + 2*k];
        w0[k] = a.x; w0[k+1] = a.y;
        ulonglong2 c = *(const ulonglong2*)&W_ih[r1 * Dd + 2*k];
        w1[k] = c.x; w1[k+1] = c.y;
    }
    const float bj0 = b_ih[r0] + b_hh[r0];
    const float bj1 = b_ih[r1] + b_hh[r1];

    const float4* xbase = (const float4*)(x + ((size_t)b * Tt + t0) * Dd);
    const int CHUNK4 = PCH * Dd / 4;

    {
        float4 pa = xbase[j], pb = xbase[j + 128];
        float4* dst = (float4*)&xsh[0][0][0];
        dst[j] = pa; dst[j + 128] = pb;
    }
    __syncthreads();

    for (int c = 0; c < 256 / PCH; c++){
        const int pb_ = c & 1;
        float4 pa, pbv;
        if (c + 1 < 256 / PCH){
            const float4* src = xbase + (size_t)(c + 1) * CHUNK4;
            pa  = src[j];
            pbv = src[j + 128];
        }

#pragma unroll 4
        for (int p = 0; p < PCH; p++){
            const ulonglong2* v = (const ulonglong2*)&xsh[pb_][p][0];
            ull a00 = 0ULL, a01 = 0ULL, a10 = 0ULL, a11 = 0ULL;
#pragma unroll
            for (int q = 0; q < 16; q++){
                ulonglong2 xx = v[q];
                fma2(a00, w0[2*q    ], xx.x);
                fma2(a01, w0[2*q + 1], xx.y);
                fma2(a10, w1[2*q    ], xx.x);
                fma2(a11, w1[2*q + 1], xx.y);
            }
            float2 p0 = unpack2(a00), p1 = unpack2(a01);
            float2 p2 = unpack2(a10), p3 = unpack2(a11);
            size_t base = ((size_t)(t0 + c * PCH + p) * Bsz + b) * 256;
            float2 o;
            o.x = bj0 + ((p0.x + p1.x) + (p0.y + p1.y));
            o.y = bj1 + ((p2.x + p3.x) + (p2.y + p3.y));
            *(float2*)&xg_buf[base + 2*j] = o;
        }

        if (c + 1 < 256 / PCH){
            float4* dst = (float4*)&xsh[pb_ ^ 1][0][0];
            dst[j] = pa; dst[j + 128] = pbv;
        }
        __syncthreads();
    }
}

// ---------------------------------------------------------------------------
// Recurrence v3 (round-12 exact — best measured ~650us).
// ---------------------------------------------------------------------------
__global__ __launch_bounds__(128, 2)
void lstm_rec_kernel(const float* __restrict__ h_init,
                     const float* __restrict__ c_init,
                     const float* __restrict__ W_hh,
                     float* __restrict__ y)
{
    const int tid  = threadIdx.x;
    const int w    = tid >> 5;
    const int l    = tid & 31;
    const int half = l >> 4;
    const int u    = (w << 4) + (l & 15);
    const int rA   = half ? (64 + u) : u;
    const int rB   = half ? (192 + u) : (128 + u);
    const int b0   = blockIdx.x * 2;

    __shared__ __align__(16) float hs[2][2][Hh];

    ull wA[Hh/2], wB[Hh/2];
#pragma unroll
    for (int k = 0; k < Hh/2; k += 2){
        ulonglong2 a = *(const ulonglong2*)&W_hh[rA * Hh + 2*k];
        wA[k] = a.x; wA[k+1] = a.y;
        ulonglong2 c = *(const ulonglong2*)&W_hh[rB * Hh + 2*k];
        wB[k] = c.x; wB[k+1] = c.y;
    }

    float creg = c_init[u];
    hs[0][half][u] = h_init[u];

    float xA0 = xg_buf[(size_t)(b0    ) * 256 + rA];
    float xB0 = xg_buf[(size_t)(b0    ) * 256 + rB];
    float xA1 = xg_buf[(size_t)(b0 + 1) * 256 + rA];
    float xB1 = xg_buf[(size_t)(b0 + 1) * 256 + rB];
    __syncthreads();

#pragma unroll 1
    for (int t = 0; t < Tt; t++){
        const int pr = t & 1;
        float cA0 = xA0, cB0 = xB0, cA1 = xA1, cB1 = xB1;
        if (t + 1 < Tt){
            size_t base = ((size_t)(t + 1) * Bsz + b0) * 256;
            xA0 = xg_buf[base + rA];
            xB0 = xg_buf[base + rB];
            xA1 = xg_buf[base + 256 + rA];
            xB1 = xg_buf[base + 256 + rB];
        }

        ull aA0a=0,aA0b=0,aB0a=0,aB0b=0,aA1a=0,aA1b=0,aB1a=0,aB1b=0;
#pragma unroll
        for (int k = 0; k < Hh; k += 4){
            ulonglong2 v0 = *(const ulonglong2*)&hs[pr][0][k];
            ulonglong2 v1 = *(const ulonglong2*)&hs[pr][1][k];
            fma2(aA0a, wA[k/2    ], v0.x);
            fma2(aA0b, wA[k/2 + 1], v0.y);
            fma2(aB0a, wB[k/2    ], v0.x);
            fma2(aB0b, wB[k/2 + 1], v0.y);
            fma2(aA1a, wA[k/2    ], v1.x);
            fma2(aA1b, wA[k/2 + 1], v1.y);
            fma2(aB1a, wB[k/2    ], v1.x);
            fma2(aB1b, wB[k/2 + 1], v1.y);
        }
        float2 q0, q1;
        q0 = unpack2(aA0a); q1 = unpack2(aA0b);
        float gA0 = cA0 + ((q0.x + q1.x) + (q0.y + q1.y));
        q0 = unpack2(aB0a); q1 = unpack2(aB0b);
        float gB0 = cB0 + ((q0.x + q1.x) + (q0.y + q1.y));
        q0 = unpack2(aA1a); q1 = unpack2(aA1b);
        float gA1 = cA1 + ((q0.x + q1.x) + (q0.y + q1.y));
        q0 = unpack2(aB1a); q1 = unpack2(aB1b);
        float gB1 = cB1 + ((q0.x + q1.x) + (q0.y + q1.y));

        float aA0 = fsigmoid(gA0);
        float aA1 = fsigmoid(gA1);
        float aB0 = half ? fsigmoid(gB0) : ftanh(gB0);
        float aB1 = half ? fsigmoid(gB1) : ftanh(gB1);

        float pA0 = __shfl_xor_sync(0xffffffffu, aA0, 16);
        float pB0 = __shfl_xor_sync(0xffffffffu, aB0, 16);
        float pA1 = __shfl_xor_sync(0xffffffffu, aA1, 16);
        float pB1 = __shfl_xor_sync(0xffffffffu, aB1, 16);

        float ig = half ? pA1 : aA0;
        float fg = half ? aA1 : pA0;
        float gg = half ? pB1 : aB0;
        float og = half ? aB1 : pB0;

        float cn = fmaf(fg, creg, ig * gg);
        creg = cn;
        float hn = og * ftanh(cn);
        hs[pr ^ 1][half][u] = hn;
        y[((size_t)(b0 + half)) * Tt * Hh + (size_t)t * Hh + u] = hn;

        __syncthreads();
    }
}

// ---------------------------------------------------------------------------
// Heads v5: 4 outputs x 4 points register tile per thread.
// Block = 64 points, 128 threads = 8 output-quads x 16 point-groups
// (thread's points: pg + 16*i -> conflict-free smem rows).
// Per k-chunk (4 floats): 4 w LDS.128 + 8 y LDS.64 feed 32 fma2 (2.7:1).
// ---------------------------------------------------------------------------
__global__ __launch_bounds__(128, 4)
void heads_kernel(const float* __restrict__ y,
                  const float* __restrict__ W1, const float* __restrict__ b1,
                  const float* __restrict__ W2, const float* __restrict__ b2,
                  const float* __restrict__ W3, const float* __restrict__ b3,
                  float* __restrict__ outs)
{
    extern __shared__ float sm[];
    float* w1r = sm;                    // 2048
    float* w2r = w1r + 2048;            // 1024
    float* w3r = w2r + 1024;            // 32
    float* b1r = w3r + 32;              // 32
    float* b2r = b1r + 32;              // 32
    float* b3r = b2r + 32;              // 8 pad
    ull*   ysp = (ull*)(sm + 3208);     // [32][66]  k2-major, pt padded
    ull*   h1s = ysp + 32*66;           // [64][17]  pt-major, m2 padded
    ull*   h2s = h1s + 64*17;           // [64][17]

    const int tid = threadIdx.x;
    const int oq  = tid >> 4;           // 0..7 -> outputs 4oq..4oq+3
    const int pg  = tid & 15;           // points pg + 16*i
    const size_t bt0 = (size_t)blockIdx.x * 64;
    const size_t BT  = (size_t)Bsz * Tt;

    // stage y (coalesced LDG.128): 1024 float4, 8 per thread
    {
        const float4* ysrc = (const float4*)(y + bt0 * Hh);
#pragma unroll
        for (int it = 0; it < 8; it++){
            int i4  = tid + it * 128;
            float4 v = ysrc[i4];
            int pt = i4 >> 4;
            int k4 = i4 & 15;
            ysp[(2*k4    ) * 66 + pt] = pack2(v.x, v.y);
            ysp[(2*k4 + 1) * 66 + pt] = pack2(v.z, v.w);
        }
    }

#pragma unroll 1
    for (int r = 0; r < Rr; r++){
        __syncthreads();                 // ysp ready (r=0) / prev r done
        {
            const float4* s1 = (const float4*)(W1 + r * 2048);
            float4* d1 = (float4*)w1r;
            d1[tid] = s1[tid]; d1[tid+128] = s1[tid+128];
            d1[tid+256] = s1[tid+256]; d1[tid+384] = s1[tid+384];
            const float4* s2 = (const float4*)(W2 + r * 1024);
            float4* d2 = (float4*)w2r;
            d2[tid] = s2[tid]; d2[tid+128] = s2[tid+128];
            if (tid < 8) ((float4*)w3r)[tid] = ((const float4*)(W3 + r * 32))[tid];
            if (tid < 32){ b1r[tid] = b1[r*32 + tid]; b2r[tid] = b2[r*32 + tid]; }
            if (tid == 0) b3r[0] = b3[r];
        }
        __syncthreads();

        // ---- layer 1: 4 outs x 4 pts, k = 64 (16 chunks of 4 floats) ----
        {
            ull acc[4][4];
#pragma unroll
            for (int o = 0; o < 4; o++)
#pragma unroll
                for (int i = 0; i < 4; i++) acc[o][i] = 0ULL;

#pragma unroll
            for (int q = 0; q < 16; q++){
                ulonglong2 w0 = *(const ulonglong2*)(w1r + (4*oq + 0) * Hh + 4*q);
                ulonglong2 w1_ = *(const ulonglong2*)(w1r + (4*oq + 1) * Hh + 4*q);
                ulonglong2 w2_ = *(const ulonglong2*)(w1r + (4*oq + 2) * Hh + 4*q);
                ulonglong2 w3_ = *(const ulonglong2*)(w1r + (4*oq + 3) * Hh + 4*q);
#pragma unroll
                for (int i = 0; i < 4; i++){
                    ull y0 = ysp[(2*q    ) * 66 + pg + 16*i];
                    ull y1 = ysp[(2*q + 1) * 66 + pg + 16*i];
                    fma2(acc[0][i], w0.x,  y0); fma2(acc[0][i], w0.y,  y1);
                    fma2(acc[1][i], w1_.x, y0); fma2(acc[1][i], w1_.y, y1);
                    fma2(acc[2][i], w2_.x, y0); fma2(acc[2][i], w2_.y, y1);
                    fma2(acc[3][i], w3_.x, y0); fma2(acc[3][i], w3_.y, y1);
                }
            }
#pragma unroll
            for (int i = 0; i < 4; i++){
                float h[4];
#pragma unroll
                for (int o = 0; o < 4; o++){
                    float2 p = unpack2(acc[o][i]);
                    h[o] = fmaxf(b1r[4*oq + o] + (p.x + p.y), 0.0f);
                }
                int pt = pg + 16*i;
                h1s[pt * 17 + 2*oq    ] = pack2(h[0], h[1]);
                h1s[pt * 17 + 2*oq + 1] = pack2(h[2], h[3]);
            }
        }
        __syncthreads();

        // ---- layer 2: 4 outs x 4 pts, k = 32 (8 chunks) ----
        {
            ull acc[4][4];
#pragma unroll
            for (int o = 0; o < 4; o++)
#pragma unroll
                for (int i = 0; i < 4; i++) acc[o][i] = 0ULL;

#pragma unroll
            for (int q = 0; q < 8; q++){
                ulonglong2 w0 = *(const ulonglong2*)(w2r + (4*oq + 0) * MHh + 4*q);
                ulonglong2 w1_ = *(const ulonglong2*)(w2r + (4*oq + 1) * MHh + 4*q);
                ulonglong2 w2_ = *(const ulonglong2*)(w2r + (4*oq + 2) * MHh + 4*q);
                ulonglong2 w3_ = *(const ulonglong2*)(w2r + (4*oq + 3) * MHh + 4*q);
#pragma unroll
                for (int i = 0; i < 4; i++){
                    int pt = pg + 16*i;
                    ull y0 = h1s[pt * 17 + 2*q    ];
                    ull y1 = h1s[pt * 17 + 2*q + 1];
                    fma2(acc[0][i], w0.x,  y0); fma2(acc[0][i], w0.y,  y1);
                    fma2(acc[1][i], w1_.x, y0); fma2(acc[1][i], w1_.y, y1);
                    fma2(acc[2][i], w2_.x, y0); fma2(acc[2][i], w2_.y, y1);
                    fma2(acc[3][i], w3_.x, y0); fma2(acc[3][i], w3_.y, y1);
                }
            }
#pragma unroll
            for (int i = 0; i < 4; i++){
                float h[4];
#pragma unroll
                for (int o = 0; o < 4; o++){
                    float2 p = unpack2(acc[o][i]);
                    h[o] = fmaxf(b2r[4*oq + o] + (p.x + p.y), 0.0f);
                }
                int pt = pg + 16*i;
                h2s[pt * 17 + 2*oq    ] = pack2(h[0], h[1]);
                h2s[pt * 17 + 2*oq + 1] = pack2(h[2], h[3]);
            }
        }
        __syncthreads();

        // ---- output layer: thread pt < 64 ----
        if (tid < 64){
            const ulonglong2* wp = (const ulonglong2*)w3r;
            ull a0 = 0ULL, a1 = 0ULL;
#pragma unroll
            for (int q = 0; q < 8; q++){
                ulonglong2 w = wp[q];
                fma2(a0, w.x, h2s[tid * 17 + 2*q    ]);
                fma2(a1, w.y, h2s[tid * 17 + 2*q + 1]);
            }
            float2 p0 = unpack2(a0), p1 = unpack2(a1);
            outs[(size_t)r * BT + bt0 + tid] = b3r[0] + ((p0.x + p1.x) + (p0.y + p1.y));
        }
    }
}

extern "C" void kernel_launch(void* const* d_in, const int* in_sizes, int n_in,
                              void* d_out, int out_size)
{
    const float* x      = (const float*)d_in[0];
    const float* h_init = (const float*)d_in[1];
    const float* c_init = (const float*)d_in[2];
    const float* W_ih   = (const float*)d_in[3];
    const float* W_hh   = (const float*)d_in[4];
    const float* b_ih   = (const float*)d_in[5];
    const float* b_hh   = (const float*)d_in[6];
    const float* W1     = (const float*)d_in[7];
    const float* b1     = (const float*)d_in[8];
    const float* W2     = (const float*)d_in[9];
    const float* b2     = (const float*)d_in[10];
    const float* W3     = (const float*)d_in[11];
    const float* b3     = (const float*)d_in[12];

    float* y    = (float*)d_out;                     // (B, T, H)
    float* outs = y + (size_t)Bsz * Tt * Hh;         // (R, B, T)

    proj_kernel<<<Bsz * 4, 128>>>(x, W_ih, b_ih, b_hh);

    lstm_rec_kernel<<<Bsz / 2, 128>>>(h_init, c_init, W_hh, y);

    // smem: 3208 floats + (32*66 + 64*17 + 64*17) ull = 3208*4 + 4288*8 = 47136 B
    const size_t shmem = 3208 * sizeof(float) + 4288 * sizeof(ull);
    cudaFuncSetAttribute(heads_kernel,
                         cudaFuncAttributeMaxDynamicSharedMemorySize, (int)shmem);
    heads_kernel<<<(Bsz * Tt) / 64, 128, shmem>>>(y, W1, b1, W2, b2, W3, b3, outs);
}